// round 9
// baseline (speedup 1.0000x reference)
#include <cuda_runtime.h>

// B=16384, D=1024. j = (i + 1 + neg_idx[i]) % B
// hinge_i = relu(1 - cos(t_i,o_i) + cos(t_j,o_i)); out = mean(hinge)
// Single fused kernel; f32x2 packed FMAs shrink the per-row compute phase so
// loads stay in flight (duty-cycle -> DRAM% up). Deterministic Q32 fixed-point
// reduction via integer atomics.

__device__ unsigned long long g_sum;    // zero at load; self-cleaned per call
__device__ unsigned int       g_count;

__device__ __forceinline__ unsigned long long fma2(unsigned long long a,
                                                   unsigned long long b,
                                                   unsigned long long c) {
    unsigned long long d;
    asm("fma.rn.f32x2 %0, %1, %2, %3;" : "=l"(d) : "l"(a), "l"(b), "l"(c));
    return d;
}

// Merge two f32x2 accumulators into one scalar: add packed, then hi+lo.
__device__ __forceinline__ float hsum2(unsigned long long a, unsigned long long b) {
    unsigned long long s;
    asm("add.rn.f32x2 %0, %1, %2;" : "=l"(s) : "l"(a), "l"(b));
    float lo, hi;
    asm("mov.b64 {%0, %1}, %2;" : "=f"(lo), "=f"(hi) : "l"(s));
    return lo + hi;
}

__device__ __forceinline__ float warp_sum(float v) {
    v += __shfl_xor_sync(0xffffffffu, v, 16);
    v += __shfl_xor_sync(0xffffffffu, v, 8);
    v += __shfl_xor_sync(0xffffffffu, v, 4);
    v += __shfl_xor_sync(0xffffffffu, v, 2);
    v += __shfl_xor_sync(0xffffffffu, v, 1);
    return v;
}

// One WARP per row, 8 warps/block. Lane: 8 x ulonglong2 (16B) chunks per
// stream -> 24 independent LDG.128. `output` stream streamed (__ldcs).
__global__ __launch_bounds__(256)
void hinge_fused_kernel(const float* __restrict__ outp,
                        const float* __restrict__ tgt,
                        const void*  __restrict__ neg,
                        float* __restrict__ out,
                        int B, int D) {
    const int wid  = threadIdx.x >> 5;
    const int lane = threadIdx.x & 31;
    const int row  = (blockIdx.x << 3) + wid;
    const bool active = (row < B);

    // --- per-warp dtype detection (no barrier, no smem): int64 iff 16
    // int64-interpreted samples all land in [0,B). int32 read as int64 gives
    // lo + hi<<32, out of range unless hi==0 (p ~ 1/16383 per sample).
    int ok = 1;
    {
        int n = (B < 32 ? B / 2 : 16);
        if (lane < n) {
            long long v = ((const long long*)neg)[lane];
            ok = (v >= 0 && v < (long long)B);
        }
    }
    const int idx64 = (__ballot_sync(0xffffffffu, ok) == 0xffffffffu);

    unsigned long long fixed = 0ull;
    if (active) {
        long long nidx;
        if (idx64) nidx = ((const long long*)neg)[row];
        else       nidx = (long long)(((const int*)neg)[row]);
        long long jj = ((long long)row + 1 + nidx) % (long long)B;
        if (jj < 0) jj += B;
        const int j = (int)jj;

        const ulonglong2* __restrict__ o2 =
            (const ulonglong2*)(outp + (size_t)row * D);
        const ulonglong2* __restrict__ t2 =
            (const ulonglong2*)(tgt + (size_t)row * D);
        const ulonglong2* __restrict__ n2 =
            (const ulonglong2*)(tgt + (size_t)j * D);

        // 5 reductions x 2 packed halves. Zero bits == {+0.f, +0.f}.
        unsigned long long to0 = 0, to1 = 0, tt0 = 0, tt1 = 0, oo0 = 0,
                           oo1 = 0, no0 = 0, no1 = 0, nn0 = 0, nn1 = 0;
        const int nvec = D >> 2;            // 16B chunks per row (256)
        #pragma unroll
        for (int k = 0; k < 8; k++) {
            int i = lane + (k << 5);
            if (i < nvec) {
                longlong2 ol = __ldcs((const longlong2*)&o2[i]);  // evict-first
                ulonglong2 tv = t2[i];
                ulonglong2 nv = n2[i];
                unsigned long long ox = (unsigned long long)ol.x;
                unsigned long long oy = (unsigned long long)ol.y;
                to0 = fma2(tv.x, ox, to0);  to1 = fma2(tv.y, oy, to1);
                tt0 = fma2(tv.x, tv.x, tt0); tt1 = fma2(tv.y, tv.y, tt1);
                oo0 = fma2(ox, ox, oo0);    oo1 = fma2(oy, oy, oo1);
                no0 = fma2(nv.x, ox, no0);  no1 = fma2(nv.y, oy, no1);
                nn0 = fma2(nv.x, nv.x, nn0); nn1 = fma2(nv.y, nv.y, nn1);
            }
        }
        // generic tail for D > 1024 (never taken at D=1024)
        for (int i = lane + 256; i < nvec; i += 32) {
            longlong2 ol = __ldcs((const longlong2*)&o2[i]);
            ulonglong2 tv = t2[i];
            ulonglong2 nv = n2[i];
            unsigned long long ox = (unsigned long long)ol.x;
            unsigned long long oy = (unsigned long long)ol.y;
            to0 = fma2(tv.x, ox, to0);  to1 = fma2(tv.y, oy, to1);
            tt0 = fma2(tv.x, tv.x, tt0); tt1 = fma2(tv.y, tv.y, tt1);
            oo0 = fma2(ox, ox, oo0);    oo1 = fma2(oy, oy, oo1);
            no0 = fma2(nv.x, ox, no0);  no1 = fma2(nv.y, oy, no1);
            nn0 = fma2(nv.x, nv.x, nn0); nn1 = fma2(nv.y, nv.y, nn1);
        }

        float d_to = warp_sum(hsum2(to0, to1));
        float n_t  = warp_sum(hsum2(tt0, tt1));
        float n_o  = warp_sum(hsum2(oo0, oo1));
        float d_no = warp_sum(hsum2(no0, no1));
        float n_n  = warp_sum(hsum2(nn0, nn1));

        if (lane == 0) {
            const float eps = 1e-6f;
            float no    = sqrtf(n_o);
            float cos_p = d_to / fmaxf(sqrtf(n_t) * no, eps);
            float cos_n = d_no / fmaxf(sqrtf(n_n) * no, eps);
            float h     = fmaxf(0.f, 1.0f - cos_p + cos_n);
            // Q32 fixed point: h in [0,3]; B*3*2^32 < 2^49.
            fixed = (unsigned long long)llrint((double)h * 4294967296.0);
        }
    }

    __shared__ unsigned long long s_part[8];
    if (lane == 0) s_part[wid] = fixed;
    __syncthreads();

    if (threadIdx.x == 0) {
        unsigned long long bs = 0ull;
        #pragma unroll
        for (int w = 0; w < 8; w++) bs += s_part[w];
        atomicAdd(&g_sum, bs);
        __threadfence();
        unsigned int c = atomicAdd(&g_count, 1u);
        if (c == gridDim.x - 1) {
            unsigned long long total = atomicAdd(&g_sum, 0ull);
            out[0] = (float)((double)total / 4294967296.0 / (double)B);
            g_sum = 0ull;     // self-clean for next graph replay
            g_count = 0u;
        }
    }
}

extern "C" void kernel_launch(void* const* d_in, const int* in_sizes, int n_in,
                              void* d_out, int out_size) {
    const float* outp = (const float*)d_in[0];   // output [B, D] f32
    const float* tgt  = (const float*)d_in[1];   // target [B, D] f32
    const void*  neg  = d_in[2];                 // neg_idx [B] int64 or int32

    const int B = in_sizes[2];
    const int D = in_sizes[0] / B;

    const int grid = (B + 7) / 8;                // one warp per row
    hinge_fused_kernel<<<grid, 256>>>(outp, tgt, neg, (float*)d_out, B, D);
}